// round 1
// baseline (speedup 1.0000x reference)
#include <cuda_runtime.h>

#define B_ROWS 8192
#define F_DIM 128
#define Q_DIM 64
#define IN_DIM 193
#define H1D 256
#define H2D 256
#define THRESH 0.95f
#define EPSV 1e-12f

// Scratch (no allocations allowed in kernel_launch)
__device__ float g_xn[B_ROWS * F_DIM];   // normalized rows
__device__ int   g_cnt[B_ROWS];          // adjacency degree counts
__device__ float g_h1[B_ROWS * H1D];
__device__ float g_h2[B_ROWS * H2D];

// ---------------------------------------------------------------------------
// Kernel 1: row L2 norm -> normalized rows; also zero the counters
// One warp per row. 256 threads = 8 rows/block.
// ---------------------------------------------------------------------------
__global__ void rownorm_kernel(const float* __restrict__ x) {
    int row  = blockIdx.x * 8 + (threadIdx.x >> 5);
    int lane = threadIdx.x & 31;
    const float4* xr = (const float4*)(x + (size_t)row * F_DIM);
    float4 v = xr[lane];                       // 32 lanes * 4 = 128 floats
    float s = v.x * v.x + v.y * v.y + v.z * v.z + v.w * v.w;
    #pragma unroll
    for (int o = 16; o > 0; o >>= 1) s += __shfl_xor_sync(0xffffffffu, s, o);
    float inv = 1.0f / (sqrtf(s) + EPSV);
    float4 o4 = make_float4(v.x * inv, v.y * inv, v.z * inv, v.w * inv);
    ((float4*)(g_xn + (size_t)row * F_DIM))[lane] = o4;
    if (lane == 0) g_cnt[row] = 0;
}

// ---------------------------------------------------------------------------
// Kernel 2: Gram count. Block computes a 128x128 tile of xn @ xn.T,
// counts fid = dot^2 >= THRESH (excluding diagonal), accumulates per-row.
// 256 threads (16x16), 8x8 micro-tile per thread (strided: m = ty+16i, n = tx+16j).
// ---------------------------------------------------------------------------
#define GBM 128
#define GBN 128
#define GBK 16

__global__ void gram_count_kernel() {
    __shared__ float As[GBM][GBK];       // [m][k]: reads are warp-broadcast
    __shared__ float Bs[GBK][GBN + 1];   // [k][n]+pad: reads are contiguous in n
    __shared__ int s_cnt[GBM];

    int t  = threadIdx.x;
    int tx = t & 15, ty = t >> 4;
    int rowBase = blockIdx.y * GBM;
    int colBase = blockIdx.x * GBN;

    if (t < GBM) s_cnt[t] = 0;

    float acc[8][8];
    #pragma unroll
    for (int i = 0; i < 8; i++)
        #pragma unroll
        for (int j = 0; j < 8; j++) acc[i][j] = 0.0f;

    for (int kk = 0; kk < F_DIM; kk += GBK) {
        // 128x16 tile each = 2048 elems; 8 per thread; consecutive t -> consecutive k (coalesced)
        #pragma unroll
        for (int l = 0; l < 8; l++) {
            int idx = t + l * 256;
            int m = idx >> 4;
            int k = idx & 15;
            As[m][k] = g_xn[(size_t)(rowBase + m) * F_DIM + kk + k];
            Bs[k][m] = g_xn[(size_t)(colBase + m) * F_DIM + kk + k];
        }
        __syncthreads();
        #pragma unroll
        for (int k = 0; k < GBK; k++) {
            float ra[8], rb[8];
            #pragma unroll
            for (int i = 0; i < 8; i++) ra[i] = As[ty + 16 * i][k];
            #pragma unroll
            for (int j = 0; j < 8; j++) rb[j] = Bs[k][tx + 16 * j];
            #pragma unroll
            for (int i = 0; i < 8; i++)
                #pragma unroll
                for (int j = 0; j < 8; j++)
                    acc[i][j] = fmaf(ra[i], rb[j], acc[i][j]);
        }
        __syncthreads();
    }

    // Count threshold hits per row
    #pragma unroll
    for (int i = 0; i < 8; i++) {
        int r   = ty + 16 * i;
        int row = rowBase + r;
        int c = 0;
        #pragma unroll
        for (int j = 0; j < 8; j++) {
            int col  = colBase + tx + 16 * j;
            float v  = acc[i][j];
            float fid = v * v;
            if (fid >= THRESH && row != col) c++;
        }
        if (c) atomicAdd(&s_cnt[r], c);
    }
    __syncthreads();
    if (t < GBM && s_cnt[t]) atomicAdd(&g_cnt[rowBase + t], s_cnt[t]);
}

// ---------------------------------------------------------------------------
// Kernel 3/4: MLP layers 1 & 2 as tiled GEMM + bias + relu.
// MODE 0: in = concat(x, q, graph) (K=193, folded into the load), W1/b1 -> g_h1
// MODE 1: in = g_h1 (K=256), W2/b2 -> g_h2
// Block: 64x64 tile, 256 threads, 4x4 micro-tile.
// ---------------------------------------------------------------------------
template <int MODE>
__global__ void mlp_kernel(const float* __restrict__ x,
                           const float* __restrict__ q,
                           const float* __restrict__ W,
                           const float* __restrict__ bias) {
    const int K = (MODE == 0) ? IN_DIM : H1D;
    __shared__ float As[64][16];
    __shared__ float Ws[16][65];

    int t  = threadIdx.x;
    int tx = t & 15, ty = t >> 4;
    int mBase = blockIdx.y * 64;
    int nBase = blockIdx.x * 64;

    float acc[4][4];
    #pragma unroll
    for (int i = 0; i < 4; i++)
        #pragma unroll
        for (int j = 0; j < 4; j++) acc[i][j] = 0.0f;

    for (int kk = 0; kk < K; kk += 16) {
        #pragma unroll
        for (int l = 0; l < 4; l++) {
            int idx = t + l * 256;
            int m = idx >> 4;
            int k = idx & 15;
            int kg = kk + k;
            int row = mBase + m;
            float av;
            if (MODE == 0) {
                if (kg < F_DIM)                 av = x[(size_t)row * F_DIM + kg];
                else if (kg < F_DIM + Q_DIM)    av = q[(size_t)row * Q_DIM + (kg - F_DIM)];
                else if (kg == IN_DIM - 1)      av = (float)g_cnt[row] * (1.0f / (float)B_ROWS);
                else                            av = 0.0f;
            } else {
                av = g_h1[(size_t)row * H1D + kg];
            }
            As[m][k] = av;
            int n = m;  // same index decomposition for the weight tile
            float wv = (kg < K) ? W[(size_t)(nBase + n) * K + kg] : 0.0f;
            Ws[k][n] = wv;
        }
        __syncthreads();
        #pragma unroll
        for (int k = 0; k < 16; k++) {
            float ra[4], rb[4];
            #pragma unroll
            for (int i = 0; i < 4; i++) ra[i] = As[ty + 16 * i][k];
            #pragma unroll
            for (int j = 0; j < 4; j++) rb[j] = Ws[k][tx + 16 * j];
            #pragma unroll
            for (int i = 0; i < 4; i++)
                #pragma unroll
                for (int j = 0; j < 4; j++)
                    acc[i][j] = fmaf(ra[i], rb[j], acc[i][j]);
        }
        __syncthreads();
    }

    float* outp = (MODE == 0) ? g_h1 : g_h2;
    #pragma unroll
    for (int i = 0; i < 4; i++) {
        int row = mBase + ty + 16 * i;
        #pragma unroll
        for (int j = 0; j < 4; j++) {
            int col = nBase + tx + 16 * j;
            float v = acc[i][j] + bias[col];
            outp[(size_t)row * 256 + col] = fmaxf(v, 0.0f);
        }
    }
}

// ---------------------------------------------------------------------------
// Kernel 5: final layer — dot(h2[row], W3) + b3. One warp per row.
// ---------------------------------------------------------------------------
__global__ void layer3_kernel(const float* __restrict__ W3,
                              const float* __restrict__ b3,
                              float* __restrict__ out) {
    int warp = threadIdx.x >> 5;
    int lane = threadIdx.x & 31;
    int row  = blockIdx.x * 8 + warp;
    const float4* h = (const float4*)(g_h2 + (size_t)row * H2D);
    const float4* w = (const float4*)W3;
    float s = 0.0f;
    #pragma unroll
    for (int l = 0; l < 2; l++) {
        float4 hv = h[lane + 32 * l];
        float4 wv = w[lane + 32 * l];
        s += hv.x * wv.x + hv.y * wv.y + hv.z * wv.z + hv.w * wv.w;
    }
    #pragma unroll
    for (int o = 16; o > 0; o >>= 1) s += __shfl_xor_sync(0xffffffffu, s, o);
    if (lane == 0) out[row] = s + b3[0];
}

// ---------------------------------------------------------------------------
extern "C" void kernel_launch(void* const* d_in, const int* in_sizes, int n_in,
                              void* d_out, int out_size) {
    const float* x  = (const float*)d_in[0];  // [8192, 128]
    const float* q  = (const float*)d_in[1];  // [8192, 64]
    const float* W1 = (const float*)d_in[2];  // [256, 193]
    const float* b1 = (const float*)d_in[3];  // [256]
    const float* W2 = (const float*)d_in[4];  // [256, 256]
    const float* b2 = (const float*)d_in[5];  // [256]
    const float* W3 = (const float*)d_in[6];  // [1, 256]
    const float* b3 = (const float*)d_in[7];  // [1]
    float* out = (float*)d_out;               // [8192]

    rownorm_kernel<<<B_ROWS / 8, 256>>>(x);
    gram_count_kernel<<<dim3(B_ROWS / GBN, B_ROWS / GBM), 256>>>();
    mlp_kernel<0><<<dim3(H1D / 64, B_ROWS / 64), 256>>>(x, q, W1, b1);
    mlp_kernel<1><<<dim3(H2D / 64, B_ROWS / 64), 256>>>(x, q, W2, b2);
    layer3_kernel<<<B_ROWS / 8, 256>>>(W3, b3, out);
}